// round 13
// baseline (speedup 1.0000x reference)
#include <cuda_runtime.h>
#include <cstdint>

// ===========================================================================
// TreeLSTMCell via mma.sync.m16n8k8.tf32 (plain sm_103 target, no tcgen05).
//
// R12 changes vs R11 (latency/issue-bound per ncu):
//  * A path: LDG.128 -> cvt.rna.tf32 -> STS.128, double-buffered smem,
//    registers staged TWO chunks ahead. Inner loop reads A as raw bits
//    (already tf32-rounded) -> zero cvt in the hot loop (was 64/thread/chunk).
//  * B path: cp.async, TRIPLE buffered, wait_group 2/1/0 taper -> two chunks
//    always in flight instead of zero.
//
// CTA = 128 nodes, 256 threads, warp grid 2(M)x4(N), warp tile 64x32.
// Five GEMM passes (N-window 128 each):
//   P0: f(ch0)=h_cat@Uf[:,0:128]   K=256 -> outC  = sig(f0)*c_ch0
//   P1: f(ch1)=h_cat@Uf[:,128:256] K=256 -> outC += sig(f1)*c_ch1
//   P2: u = A@Wc[:,256:384] K=384 -> outH = tanh(u+b)
//   P3: i = A@Wc[:,0:128]   K=384 -> outC = sig(i+b)*outH + outC
//   P4: o = A@Wc[:,128:256] K=384 -> outH = sig(o+b)*tanh(outC)
// A row (P2-4) = leaf ? [0,0,x] : [h_ch0,h_ch1,0]; Wc = [U_iou|W_iou] tf32.
// ===========================================================================

#define HH   128
#define KC   32
#define PADK 36              // row stride (floats); %32==4 -> conflict-free LDS
#define A_SLOT 18432         // 128*36*4
#define B_SLOT 18432
#define A_OFF  0             // 2 slots
#define B_OFF  (2*A_SLOT)    // 3 slots
#define META_OFF (B_OFF + 3*B_SLOT)
#define SMEM_BYTES (META_OFF + 5632)

__device__ float g_Wf[256 * 256];     // Uf tf32-rounded, [o][k]
__device__ float g_Wiou[384 * 384];   // [U_iou | W_iou] tf32-rounded

__device__ __forceinline__ uint32_t cvt_tf32(float f) {
    uint32_t r;
    asm("cvt.rna.tf32.f32 %0, %1;" : "=r"(r) : "f"(f));
    return r;
}

__global__ void prep_kernel(const float* __restrict__ Uf,
                            const float* __restrict__ Uiou,
                            const float* __restrict__ Wiou) {
    int i = blockIdx.x * blockDim.x + threadIdx.x;
    if (i < 256 * 256) g_Wf[i] = __uint_as_float(cvt_tf32(Uf[i]));
    int j = i - 256 * 256;
    if (j >= 0 && j < 384 * 384) {
        int o = j / 384, k = j - o * 384;
        float v = (k < 256) ? Uiou[o * 256 + k] : Wiou[o * 128 + (k - 256)];
        g_Wiou[j] = __uint_as_float(cvt_tf32(v));
    }
}

__device__ __forceinline__ uint32_t smem_u32(const void* p) {
    uint32_t a;
    asm("{ .reg .u64 t; cvta.to.shared.u64 t, %1; cvt.u32.u64 %0, t; }"
        : "=r"(a) : "l"(p));
    return a;
}
__device__ __forceinline__ void cpa16(uint32_t dst, const void* src) {
    asm volatile("cp.async.ca.shared.global [%0], [%1], 16;"
                 :: "r"(dst), "l"(src) : "memory");
}
#define CP_COMMIT() asm volatile("cp.async.commit_group;" ::: "memory")
#define WAITG(n)    asm volatile("cp.async.wait_group %0;" :: "n"(n) : "memory")

__device__ __forceinline__ void mma8(float d[4], const uint32_t a[4],
                                     const uint32_t b[2]) {
    asm volatile(
        "mma.sync.aligned.m16n8k8.row.col.f32.tf32.tf32.f32 "
        "{%0,%1,%2,%3}, {%4,%5,%6,%7}, {%8,%9}, {%0,%1,%2,%3};"
        : "+f"(d[0]), "+f"(d[1]), "+f"(d[2]), "+f"(d[3])
        : "r"(a[0]), "r"(a[1]), "r"(a[2]), "r"(a[3]), "r"(b[0]), "r"(b[1]));
}
__device__ __forceinline__ float sigm(float v) { return 1.0f / (1.0f + __expf(-v)); }

// ---- A: global -> regs (gather + leaf masking) ----
template <int TYPE>
__device__ __forceinline__ void ldgA(float4 (&v)[4], int kc,
                                     const float* __restrict__ h,
                                     const float* __restrict__ x,
                                     const int* sCh, const int* sLf,
                                     int base, int tid) {
#pragma unroll
    for (int r = 0; r < 4; r++) {
        int idx = tid + r * 256;
        int m = idx >> 3, seg = idx & 7;
        int k = kc * KC + seg * 4;
        if (TYPE == 0) {
            v[r] = *(const float4*)(h + (size_t)sCh[2 * m + (k >> 7)] * HH + (k & 127));
        } else {
            int leaf = sLf[m];
            float4 t = make_float4(0.f, 0.f, 0.f, 0.f);
            if (k < 256) {
                if (!leaf)
                    t = *(const float4*)(h + (size_t)sCh[2 * m + (k >> 7)] * HH + (k & 127));
            } else {
                if (leaf)
                    t = *(const float4*)(x + (size_t)(base + m) * HH + (k - 256));
            }
            v[r] = t;
        }
    }
}

// ---- A: regs -> tf32-rounded -> smem (STS.128, conflict-free per phase) ----
__device__ __forceinline__ void cvtstsA(const float4 (&v)[4], char* dst, int tid) {
#pragma unroll
    for (int r = 0; r < 4; r++) {
        int idx = tid + r * 256;
        int m = idx >> 3, seg = idx & 7;
        uint4 u;
        u.x = cvt_tf32(v[r].x); u.y = cvt_tf32(v[r].y);
        u.z = cvt_tf32(v[r].z); u.w = cvt_tf32(v[r].w);
        *(uint4*)(dst + (m * PADK + seg * 4) * 4) = u;
    }
}

// ---- B: global -> smem via cp.async ----
__device__ __forceinline__ void loadB(const float* __restrict__ W, int ldw,
                                      int nb, char* dst, int kc, int tid) {
#pragma unroll
    for (int r = 0; r < 4; r++) {
        int idx = tid + r * 256;
        int n = idx >> 3, s = idx & 7;
        cpa16(smem_u32(dst + (n * PADK + s * 4) * 4),
              W + (size_t)(nb + n) * ldw + kc * KC + s * 4);
    }
}

// ---- one K=32 chunk: 64 HMMA/warp, zero cvt (A pre-rounded in smem) ----
__device__ __forceinline__ void compute_chunk(const float* sA, const float* sB,
                                              float acc[4][4][4],
                                              int wm, int wn, int g, int t) {
#pragma unroll
    for (int kk = 0; kk < 4; kk++) {
        uint32_t af[4][4];
#pragma unroll
        for (int mt = 0; mt < 4; mt++) {
            const float* ap = sA + (wm * 64 + mt * 16 + g) * PADK + kk * 8 + t;
            af[mt][0] = __float_as_uint(ap[0]);
            af[mt][1] = __float_as_uint(ap[8 * PADK]);
            af[mt][2] = __float_as_uint(ap[4]);
            af[mt][3] = __float_as_uint(ap[8 * PADK + 4]);
        }
        uint32_t bf[4][2];
#pragma unroll
        for (int nt = 0; nt < 4; nt++) {
            const float* bp = sB + (wn * 32 + nt * 8 + g) * PADK + kk * 8 + t;
            bf[nt][0] = __float_as_uint(bp[0]);
            bf[nt][1] = __float_as_uint(bp[4]);
        }
#pragma unroll
        for (int mt = 0; mt < 4; mt++)
#pragma unroll
            for (int nt = 0; nt < 4; nt++)
                mma8(acc[mt][nt], af[mt], bf[nt]);
    }
}

// ---- per-pass epilogue (same lane->(row,col) mapping every pass) ----
template <int PASS>
__device__ __forceinline__ void epilogue(float acc[4][4][4],
                                         const float* __restrict__ c,
                                         const int* sCh, const int* sLf,
                                         const float* sbUf, const float* sbI,
                                         const float* sbW,
                                         float* __restrict__ outH,
                                         float* __restrict__ outC,
                                         int base, int wm, int wn, int g, int t) {
#pragma unroll
    for (int mt = 0; mt < 4; mt++) {
#pragma unroll
        for (int hr = 0; hr < 2; hr++) {
            int row = wm * 64 + mt * 16 + hr * 8 + g;
            size_t node = (size_t)(base + row);
            const float* bb = sLf[row] ? sbW : sbI;
            const float* crow = c;
            if (PASS == 0) crow = c + (size_t)sCh[2 * row] * HH;
            if (PASS == 1) crow = c + (size_t)sCh[2 * row + 1] * HH;
#pragma unroll
            for (int nt = 0; nt < 4; nt++) {
                int col = wn * 32 + nt * 8 + 2 * t;
                float v0 = acc[mt][nt][hr * 2 + 0];
                float v1 = acc[mt][nt][hr * 2 + 1];
                if (PASS == 0) {
                    float2 cc = *(const float2*)(crow + col);
                    float2 r = make_float2(sigm(v0 + sbUf[col]) * cc.x,
                                           sigm(v1 + sbUf[col + 1]) * cc.y);
                    *(float2*)(outC + node * HH + col) = r;
                } else if (PASS == 1) {
                    float2 cc = *(const float2*)(crow + col);
                    float2 old = *(const float2*)(outC + node * HH + col);
                    float2 r = make_float2(
                        old.x + sigm(v0 + sbUf[128 + col]) * cc.x,
                        old.y + sigm(v1 + sbUf[128 + col + 1]) * cc.y);
                    *(float2*)(outC + node * HH + col) = r;
                } else if (PASS == 2) {
                    float2 r = make_float2(tanhf(v0 + bb[256 + col]),
                                           tanhf(v1 + bb[256 + col + 1]));
                    *(float2*)(outH + node * HH + col) = r;
                } else if (PASS == 3) {
                    float2 tu = *(const float2*)(outH + node * HH + col);
                    float2 cf = *(const float2*)(outC + node * HH + col);
                    float2 r = make_float2(sigm(v0 + bb[col]) * tu.x + cf.x,
                                           sigm(v1 + bb[col + 1]) * tu.y + cf.y);
                    *(float2*)(outC + node * HH + col) = r;
                } else {
                    float2 cn = *(const float2*)(outC + node * HH + col);
                    float2 r = make_float2(
                        sigm(v0 + bb[128 + col]) * tanhf(cn.x),
                        sigm(v1 + bb[128 + col + 1]) * tanhf(cn.y));
                    *(float2*)(outH + node * HH + col) = r;
                }
            }
        }
    }
}

template <int PASS, int ATYPE, int NK>
__device__ __forceinline__ void run_pass(char* smem,
                                         const float* __restrict__ W, int ldw, int nb,
                                         const float* __restrict__ h,
                                         const float* __restrict__ x,
                                         const float* __restrict__ c,
                                         const int* sCh, const int* sLf,
                                         const float* sbUf, const float* sbI,
                                         const float* sbW,
                                         float* outH, float* outC, int base,
                                         int tid, int wm, int wn, int g, int t) {
    float acc[4][4][4];
#pragma unroll
    for (int a1 = 0; a1 < 4; a1++)
#pragma unroll
        for (int a2 = 0; a2 < 4; a2++)
#pragma unroll
            for (int a3 = 0; a3 < 4; a3++) acc[a1][a2][a3] = 0.f;

    __syncthreads();   // previous pass fully out of A/B smem

    // prologue: B chunks 0,1 in flight; A chunk 0 in smem; A chunk 1 in regs
    loadB(W, ldw, nb, smem + B_OFF + 0 * B_SLOT, 0, tid);
    CP_COMMIT();
    loadB(W, ldw, nb, smem + B_OFF + 1 * B_SLOT, 1, tid);
    CP_COMMIT();
    float4 vr[4];
    ldgA<ATYPE>(vr, 0, h, x, sCh, sLf, base, tid);
    cvtstsA(vr, smem + A_OFF, tid);
    ldgA<ATYPE>(vr, 1, h, x, sCh, sLf, base, tid);

#pragma unroll 1
    for (int kc = 0; kc < NK; kc++) {
        int rem = NK - 1 - kc;
        if (rem >= 2)      { WAITG(2); }
        else if (rem == 1) { WAITG(1); }
        else               { WAITG(0); }
        __syncthreads();   // B(kc) visible to all; A(kc) STS'd last iter visible;
                           // all warps done with A slot (kc+1)&1 and B slot (kc+2)%3
        if (kc + 1 < NK)
            cvtstsA(vr, smem + A_OFF + ((kc + 1) & 1) * A_SLOT, tid);
        if (kc + 2 < NK) {
            ldgA<ATYPE>(vr, kc + 2, h, x, sCh, sLf, base, tid);
            loadB(W, ldw, nb, smem + B_OFF + ((kc + 2) % 3) * B_SLOT, kc + 2, tid);
            CP_COMMIT();
        }
        compute_chunk((const float*)(smem + A_OFF + (kc & 1) * A_SLOT),
                      (const float*)(smem + B_OFF + (kc % 3) * B_SLOT),
                      acc, wm, wn, g, t);
    }
    epilogue<PASS>(acc, c, sCh, sLf, sbUf, sbI, sbW, outH, outC,
                   base, wm, wn, g, t);
}

__global__ void __launch_bounds__(256, 2)
tree_kernel(const float* __restrict__ x, const float* __restrict__ h,
            const float* __restrict__ c, const int* __restrict__ children,
            const int* __restrict__ is_leaf,
            const float* __restrict__ bWiou, const float* __restrict__ bUiou,
            const float* __restrict__ bUf,
            float* __restrict__ out, int N) {
    extern __shared__ char smem[];
    int*   sCh  = (int*)(smem + META_OFF);
    int*   sLf  = (int*)(smem + META_OFF + 1024);
    float* sbUf = (float*)(smem + META_OFF + 1536);
    float* sbI  = (float*)(smem + META_OFF + 2560);
    float* sbW  = (float*)(smem + META_OFF + 4096);

    const int tid = threadIdx.x;
    const int wid = tid >> 5, lane = tid & 31;
    const int g = lane >> 2, t = lane & 3;
    const int wm = wid >> 2, wn = wid & 3;
    const int base = blockIdx.x * 128;

    sCh[tid] = children[base * 2 + tid];
    sbUf[tid] = bUf[tid];
    sbI[tid] = bUiou[tid];
    sbW[tid] = bWiou[tid];
    if (tid < 128) {
        sLf[tid] = is_leaf[base + tid];
        sbI[256 + tid] = bUiou[256 + tid];
        sbW[256 + tid] = bWiou[256 + tid];
    }
    __syncthreads();

    float* outH = out;
    float* outC = out + (size_t)N * HH;

    run_pass<0, 0, 8>(smem, g_Wf, 256, 0, h, x, c, sCh, sLf, sbUf, sbI, sbW,
                      outH, outC, base, tid, wm, wn, g, t);
    run_pass<1, 0, 8>(smem, g_Wf, 256, 128, h, x, c, sCh, sLf, sbUf, sbI, sbW,
                      outH, outC, base, tid, wm, wn, g, t);
    run_pass<2, 1, 12>(smem, g_Wiou, 384, 256, h, x, c, sCh, sLf, sbUf, sbI, sbW,
                       outH, outC, base, tid, wm, wn, g, t);
    run_pass<3, 1, 12>(smem, g_Wiou, 384, 0, h, x, c, sCh, sLf, sbUf, sbI, sbW,
                       outH, outC, base, tid, wm, wn, g, t);
    run_pass<4, 1, 12>(smem, g_Wiou, 384, 128, h, x, c, sCh, sLf, sbUf, sbI, sbW,
                       outH, outC, base, tid, wm, wn, g, t);
}

extern "C" void kernel_launch(void* const* d_in, const int* in_sizes, int n_in,
                              void* d_out, int out_size) {
    const float* x        = (const float*)d_in[0];
    const float* h        = (const float*)d_in[1];
    const float* c        = (const float*)d_in[2];
    const int*   children = (const int*)d_in[3];
    const int*   is_leaf  = (const int*)d_in[4];
    const float* W_iou    = (const float*)d_in[5];
    const float* b_Wiou   = (const float*)d_in[6];
    const float* U_iou    = (const float*)d_in[7];
    const float* b_Uiou   = (const float*)d_in[8];
    const float* U_f      = (const float*)d_in[9];
    const float* b_Uf     = (const float*)d_in[10];

    int N = in_sizes[1] / HH;   // 400000, multiple of 128

    cudaFuncSetAttribute(tree_kernel,
                         cudaFuncAttributeMaxDynamicSharedMemorySize, SMEM_BYTES);

    prep_kernel<<<(256 * 256 + 384 * 384 + 255) / 256, 256>>>(U_f, U_iou, W_iou);
    tree_kernel<<<N / 128, 256, SMEM_BYTES>>>(x, h, c, children, is_leaf,
                                              b_Wiou, b_Uiou, b_Uf,
                                              (float*)d_out, N);
}

// round 14
// speedup vs baseline: 1.0004x; 1.0004x over previous
#include <cuda_runtime.h>
#include <cstdint>

// ===========================================================================
// TreeLSTMCell via mma.sync.m16n8k8.tf32 (plain sm_103 target, no tcgen05).
//
// R12 changes vs R11 (latency/issue-bound per ncu):
//  * A path: LDG.128 -> cvt.rna.tf32 -> STS.128, double-buffered smem,
//    registers staged TWO chunks ahead. Inner loop reads A as raw bits
//    (already tf32-rounded) -> zero cvt in the hot loop (was 64/thread/chunk).
//  * B path: cp.async, TRIPLE buffered, wait_group 2/1/0 taper -> two chunks
//    always in flight instead of zero.
//
// CTA = 128 nodes, 256 threads, warp grid 2(M)x4(N), warp tile 64x32.
// Five GEMM passes (N-window 128 each):
//   P0: f(ch0)=h_cat@Uf[:,0:128]   K=256 -> outC  = sig(f0)*c_ch0
//   P1: f(ch1)=h_cat@Uf[:,128:256] K=256 -> outC += sig(f1)*c_ch1
//   P2: u = A@Wc[:,256:384] K=384 -> outH = tanh(u+b)
//   P3: i = A@Wc[:,0:128]   K=384 -> outC = sig(i+b)*outH + outC
//   P4: o = A@Wc[:,128:256] K=384 -> outH = sig(o+b)*tanh(outC)
// A row (P2-4) = leaf ? [0,0,x] : [h_ch0,h_ch1,0]; Wc = [U_iou|W_iou] tf32.
// ===========================================================================

#define HH   128
#define KC   32
#define PADK 36              // row stride (floats); %32==4 -> conflict-free LDS
#define A_SLOT 18432         // 128*36*4
#define B_SLOT 18432
#define A_OFF  0             // 2 slots
#define B_OFF  (2*A_SLOT)    // 3 slots
#define META_OFF (B_OFF + 3*B_SLOT)
#define SMEM_BYTES (META_OFF + 5632)

__device__ float g_Wf[256 * 256];     // Uf tf32-rounded, [o][k]
__device__ float g_Wiou[384 * 384];   // [U_iou | W_iou] tf32-rounded

__device__ __forceinline__ uint32_t cvt_tf32(float f) {
    uint32_t r;
    asm("cvt.rna.tf32.f32 %0, %1;" : "=r"(r) : "f"(f));
    return r;
}

__global__ void prep_kernel(const float* __restrict__ Uf,
                            const float* __restrict__ Uiou,
                            const float* __restrict__ Wiou) {
    int i = blockIdx.x * blockDim.x + threadIdx.x;
    if (i < 256 * 256) g_Wf[i] = __uint_as_float(cvt_tf32(Uf[i]));
    int j = i - 256 * 256;
    if (j >= 0 && j < 384 * 384) {
        int o = j / 384, k = j - o * 384;
        float v = (k < 256) ? Uiou[o * 256 + k] : Wiou[o * 128 + (k - 256)];
        g_Wiou[j] = __uint_as_float(cvt_tf32(v));
    }
}

__device__ __forceinline__ uint32_t smem_u32(const void* p) {
    uint32_t a;
    asm("{ .reg .u64 t; cvta.to.shared.u64 t, %1; cvt.u32.u64 %0, t; }"
        : "=r"(a) : "l"(p));
    return a;
}
__device__ __forceinline__ void cpa16(uint32_t dst, const void* src) {
    asm volatile("cp.async.ca.shared.global [%0], [%1], 16;"
                 :: "r"(dst), "l"(src) : "memory");
}
#define CP_COMMIT() asm volatile("cp.async.commit_group;" ::: "memory")
#define WAITG(n)    asm volatile("cp.async.wait_group %0;" :: "n"(n) : "memory")

__device__ __forceinline__ void mma8(float d[4], const uint32_t a[4],
                                     const uint32_t b[2]) {
    asm volatile(
        "mma.sync.aligned.m16n8k8.row.col.f32.tf32.tf32.f32 "
        "{%0,%1,%2,%3}, {%4,%5,%6,%7}, {%8,%9}, {%0,%1,%2,%3};"
        : "+f"(d[0]), "+f"(d[1]), "+f"(d[2]), "+f"(d[3])
        : "r"(a[0]), "r"(a[1]), "r"(a[2]), "r"(a[3]), "r"(b[0]), "r"(b[1]));
}
__device__ __forceinline__ float sigm(float v) { return 1.0f / (1.0f + __expf(-v)); }

// ---- A: global -> regs (gather + leaf masking) ----
template <int TYPE>
__device__ __forceinline__ void ldgA(float4 (&v)[4], int kc,
                                     const float* __restrict__ h,
                                     const float* __restrict__ x,
                                     const int* sCh, const int* sLf,
                                     int base, int tid) {
#pragma unroll
    for (int r = 0; r < 4; r++) {
        int idx = tid + r * 256;
        int m = idx >> 3, seg = idx & 7;
        int k = kc * KC + seg * 4;
        if (TYPE == 0) {
            v[r] = *(const float4*)(h + (size_t)sCh[2 * m + (k >> 7)] * HH + (k & 127));
        } else {
            int leaf = sLf[m];
            float4 t = make_float4(0.f, 0.f, 0.f, 0.f);
            if (k < 256) {
                if (!leaf)
                    t = *(const float4*)(h + (size_t)sCh[2 * m + (k >> 7)] * HH + (k & 127));
            } else {
                if (leaf)
                    t = *(const float4*)(x + (size_t)(base + m) * HH + (k - 256));
            }
            v[r] = t;
        }
    }
}

// ---- A: regs -> tf32-rounded -> smem (STS.128, conflict-free per phase) ----
__device__ __forceinline__ void cvtstsA(const float4 (&v)[4], char* dst, int tid) {
#pragma unroll
    for (int r = 0; r < 4; r++) {
        int idx = tid + r * 256;
        int m = idx >> 3, seg = idx & 7;
        uint4 u;
        u.x = cvt_tf32(v[r].x); u.y = cvt_tf32(v[r].y);
        u.z = cvt_tf32(v[r].z); u.w = cvt_tf32(v[r].w);
        *(uint4*)(dst + (m * PADK + seg * 4) * 4) = u;
    }
}

// ---- B: global -> smem via cp.async ----
__device__ __forceinline__ void loadB(const float* __restrict__ W, int ldw,
                                      int nb, char* dst, int kc, int tid) {
#pragma unroll
    for (int r = 0; r < 4; r++) {
        int idx = tid + r * 256;
        int n = idx >> 3, s = idx & 7;
        cpa16(smem_u32(dst + (n * PADK + s * 4) * 4),
              W + (size_t)(nb + n) * ldw + kc * KC + s * 4);
    }
}

// ---- one K=32 chunk: 64 HMMA/warp, zero cvt (A pre-rounded in smem) ----
__device__ __forceinline__ void compute_chunk(const float* sA, const float* sB,
                                              float acc[4][4][4],
                                              int wm, int wn, int g, int t) {
#pragma unroll
    for (int kk = 0; kk < 4; kk++) {
        uint32_t af[4][4];
#pragma unroll
        for (int mt = 0; mt < 4; mt++) {
            const float* ap = sA + (wm * 64 + mt * 16 + g) * PADK + kk * 8 + t;
            af[mt][0] = __float_as_uint(ap[0]);
            af[mt][1] = __float_as_uint(ap[8 * PADK]);
            af[mt][2] = __float_as_uint(ap[4]);
            af[mt][3] = __float_as_uint(ap[8 * PADK + 4]);
        }
        uint32_t bf[4][2];
#pragma unroll
        for (int nt = 0; nt < 4; nt++) {
            const float* bp = sB + (wn * 32 + nt * 8 + g) * PADK + kk * 8 + t;
            bf[nt][0] = __float_as_uint(bp[0]);
            bf[nt][1] = __float_as_uint(bp[4]);
        }
#pragma unroll
        for (int mt = 0; mt < 4; mt++)
#pragma unroll
            for (int nt = 0; nt < 4; nt++)
                mma8(acc[mt][nt], af[mt], bf[nt]);
    }
}

// ---- per-pass epilogue (same lane->(row,col) mapping every pass) ----
template <int PASS>
__device__ __forceinline__ void epilogue(float acc[4][4][4],
                                         const float* __restrict__ c,
                                         const int* sCh, const int* sLf,
                                         const float* sbUf, const float* sbI,
                                         const float* sbW,
                                         float* __restrict__ outH,
                                         float* __restrict__ outC,
                                         int base, int wm, int wn, int g, int t) {
#pragma unroll
    for (int mt = 0; mt < 4; mt++) {
#pragma unroll
        for (int hr = 0; hr < 2; hr++) {
            int row = wm * 64 + mt * 16 + hr * 8 + g;
            size_t node = (size_t)(base + row);
            const float* bb = sLf[row] ? sbW : sbI;
            const float* crow = c;
            if (PASS == 0) crow = c + (size_t)sCh[2 * row] * HH;
            if (PASS == 1) crow = c + (size_t)sCh[2 * row + 1] * HH;
#pragma unroll
            for (int nt = 0; nt < 4; nt++) {
                int col = wn * 32 + nt * 8 + 2 * t;
                float v0 = acc[mt][nt][hr * 2 + 0];
                float v1 = acc[mt][nt][hr * 2 + 1];
                if (PASS == 0) {
                    float2 cc = *(const float2*)(crow + col);
                    float2 r = make_float2(sigm(v0 + sbUf[col]) * cc.x,
                                           sigm(v1 + sbUf[col + 1]) * cc.y);
                    *(float2*)(outC + node * HH + col) = r;
                } else if (PASS == 1) {
                    float2 cc = *(const float2*)(crow + col);
                    float2 old = *(const float2*)(outC + node * HH + col);
                    float2 r = make_float2(
                        old.x + sigm(v0 + sbUf[128 + col]) * cc.x,
                        old.y + sigm(v1 + sbUf[128 + col + 1]) * cc.y);
                    *(float2*)(outC + node * HH + col) = r;
                } else if (PASS == 2) {
                    float2 r = make_float2(tanhf(v0 + bb[256 + col]),
                                           tanhf(v1 + bb[256 + col + 1]));
                    *(float2*)(outH + node * HH + col) = r;
                } else if (PASS == 3) {
                    float2 tu = *(const float2*)(outH + node * HH + col);
                    float2 cf = *(const float2*)(outC + node * HH + col);
                    float2 r = make_float2(sigm(v0 + bb[col]) * tu.x + cf.x,
                                           sigm(v1 + bb[col + 1]) * tu.y + cf.y);
                    *(float2*)(outC + node * HH + col) = r;
                } else {
                    float2 cn = *(const float2*)(outC + node * HH + col);
                    float2 r = make_float2(
                        sigm(v0 + bb[128 + col]) * tanhf(cn.x),
                        sigm(v1 + bb[128 + col + 1]) * tanhf(cn.y));
                    *(float2*)(outH + node * HH + col) = r;
                }
            }
        }
    }
}

template <int PASS, int ATYPE, int NK>
__device__ __forceinline__ void run_pass(char* smem,
                                         const float* __restrict__ W, int ldw, int nb,
                                         const float* __restrict__ h,
                                         const float* __restrict__ x,
                                         const float* __restrict__ c,
                                         const int* sCh, const int* sLf,
                                         const float* sbUf, const float* sbI,
                                         const float* sbW,
                                         float* outH, float* outC, int base,
                                         int tid, int wm, int wn, int g, int t) {
    float acc[4][4][4];
#pragma unroll
    for (int a1 = 0; a1 < 4; a1++)
#pragma unroll
        for (int a2 = 0; a2 < 4; a2++)
#pragma unroll
            for (int a3 = 0; a3 < 4; a3++) acc[a1][a2][a3] = 0.f;

    __syncthreads();   // previous pass fully out of A/B smem

    // prologue: B chunks 0,1 in flight; A chunk 0 in smem; A chunk 1 in regs
    loadB(W, ldw, nb, smem + B_OFF + 0 * B_SLOT, 0, tid);
    CP_COMMIT();
    loadB(W, ldw, nb, smem + B_OFF + 1 * B_SLOT, 1, tid);
    CP_COMMIT();
    float4 vr[4];
    ldgA<ATYPE>(vr, 0, h, x, sCh, sLf, base, tid);
    cvtstsA(vr, smem + A_OFF, tid);
    ldgA<ATYPE>(vr, 1, h, x, sCh, sLf, base, tid);

#pragma unroll 1
    for (int kc = 0; kc < NK; kc++) {
        int rem = NK - 1 - kc;
        if (rem >= 2)      { WAITG(2); }
        else if (rem == 1) { WAITG(1); }
        else               { WAITG(0); }
        __syncthreads();   // B(kc) visible to all; A(kc) STS'd last iter visible;
                           // all warps done with A slot (kc+1)&1 and B slot (kc+2)%3
        if (kc + 1 < NK)
            cvtstsA(vr, smem + A_OFF + ((kc + 1) & 1) * A_SLOT, tid);
        if (kc + 2 < NK) {
            ldgA<ATYPE>(vr, kc + 2, h, x, sCh, sLf, base, tid);
            loadB(W, ldw, nb, smem + B_OFF + ((kc + 2) % 3) * B_SLOT, kc + 2, tid);
            CP_COMMIT();
        }
        compute_chunk((const float*)(smem + A_OFF + (kc & 1) * A_SLOT),
                      (const float*)(smem + B_OFF + (kc % 3) * B_SLOT),
                      acc, wm, wn, g, t);
    }
    epilogue<PASS>(acc, c, sCh, sLf, sbUf, sbI, sbW, outH, outC,
                   base, wm, wn, g, t);
}

__global__ void __launch_bounds__(256, 2)
tree_kernel(const float* __restrict__ x, const float* __restrict__ h,
            const float* __restrict__ c, const int* __restrict__ children,
            const int* __restrict__ is_leaf,
            const float* __restrict__ bWiou, const float* __restrict__ bUiou,
            const float* __restrict__ bUf,
            float* __restrict__ out, int N) {
    extern __shared__ char smem[];
    int*   sCh  = (int*)(smem + META_OFF);
    int*   sLf  = (int*)(smem + META_OFF + 1024);
    float* sbUf = (float*)(smem + META_OFF + 1536);
    float* sbI  = (float*)(smem + META_OFF + 2560);
    float* sbW  = (float*)(smem + META_OFF + 4096);

    const int tid = threadIdx.x;
    const int wid = tid >> 5, lane = tid & 31;
    const int g = lane >> 2, t = lane & 3;
    const int wm = wid >> 2, wn = wid & 3;
    const int base = blockIdx.x * 128;

    sCh[tid] = children[base * 2 + tid];
    sbUf[tid] = bUf[tid];
    sbI[tid] = bUiou[tid];
    sbW[tid] = bWiou[tid];
    if (tid < 128) {
        sLf[tid] = is_leaf[base + tid];
        sbI[256 + tid] = bUiou[256 + tid];
        sbW[256 + tid] = bWiou[256 + tid];
    }
    __syncthreads();

    float* outH = out;
    float* outC = out + (size_t)N * HH;

    run_pass<0, 0, 8>(smem, g_Wf, 256, 0, h, x, c, sCh, sLf, sbUf, sbI, sbW,
                      outH, outC, base, tid, wm, wn, g, t);
    run_pass<1, 0, 8>(smem, g_Wf, 256, 128, h, x, c, sCh, sLf, sbUf, sbI, sbW,
                      outH, outC, base, tid, wm, wn, g, t);
    run_pass<2, 1, 12>(smem, g_Wiou, 384, 256, h, x, c, sCh, sLf, sbUf, sbI, sbW,
                       outH, outC, base, tid, wm, wn, g, t);
    run_pass<3, 1, 12>(smem, g_Wiou, 384, 0, h, x, c, sCh, sLf, sbUf, sbI, sbW,
                       outH, outC, base, tid, wm, wn, g, t);
    run_pass<4, 1, 12>(smem, g_Wiou, 384, 128, h, x, c, sCh, sLf, sbUf, sbI, sbW,
                       outH, outC, base, tid, wm, wn, g, t);
}

extern "C" void kernel_launch(void* const* d_in, const int* in_sizes, int n_in,
                              void* d_out, int out_size) {
    const float* x        = (const float*)d_in[0];
    const float* h        = (const float*)d_in[1];
    const float* c        = (const float*)d_in[2];
    const int*   children = (const int*)d_in[3];
    const int*   is_leaf  = (const int*)d_in[4];
    const float* W_iou    = (const float*)d_in[5];
    const float* b_Wiou   = (const float*)d_in[6];
    const float* U_iou    = (const float*)d_in[7];
    const float* b_Uiou   = (const float*)d_in[8];
    const float* U_f      = (const float*)d_in[9];
    const float* b_Uf     = (const float*)d_in[10];

    int N = in_sizes[1] / HH;   // 400000, multiple of 128

    cudaFuncSetAttribute(tree_kernel,
                         cudaFuncAttributeMaxDynamicSharedMemorySize, SMEM_BYTES);

    prep_kernel<<<(256 * 256 + 384 * 384 + 255) / 256, 256>>>(U_f, U_iou, W_iou);
    tree_kernel<<<N / 128, 256, SMEM_BYTES>>>(x, h, c, children, is_leaf,
                                              b_Wiou, b_Uiou, b_Uf,
                                              (float*)d_out, N);
}

// round 15
// speedup vs baseline: 1.0455x; 1.0450x over previous
#include <cuda_runtime.h>
#include <cstdint>

// ===========================================================================
// TreeLSTMCell via mma.sync.m16n8k8.tf32 (plain sm_103 target).
//
// R15 vs R12/R11 (issue-mix-bound: tensor% == MMA instruction share):
//  * A back to cp.async (async gather + zfill leaf masking), NO in-loop cvt:
//    raw fp32 bits fed to tf32 MMA (HW truncation). B stays RNA pre-rounded
//    in prep -> only A truncates. Hot loop = LDS + MMA only.
//  * A and B both TRIPLE buffered, one commit group per chunk,
//    wait_group 1/0 taper -> 2 chunks of async cover, no reg staging.
//  * Biases read via __ldg in epilogue (frees smem) -> 2 CTAs/SM kept.
//
// CTA = 128 nodes, 256 threads, warp grid 2(M)x4(N), warp tile 64x32.
// Passes: P0 f(ch0) K=256 | P1 f(ch1) K=256 | P2 u K=384 | P3 i K=384 |
//         P4 o K=384.  A row (P2-4) = leaf ? [0,0,x] : [h_ch0,h_ch1,0].
// Inter-pass scalars ride in d_out (same lane->(row,col) mapping each pass).
// ===========================================================================

#define HH   128
#define KC   32
#define PADK 36                  // %32==4 -> conflict-free LDS pattern
#define SLOT 18432               // 128*36*4
#define A_OFF 0                  // 3 slots
#define B_OFF (3*SLOT)           // 3 slots
#define META_OFF (6*SLOT)        // sCh 1024B + sLf 512B
#define SMEM_BYTES (META_OFF + 1536)

__device__ float g_Wf[256 * 256];     // Uf tf32-rounded (RNA), [o][k]
__device__ float g_Wiou[384 * 384];   // [U_iou | W_iou] tf32-rounded (RNA)

__device__ __forceinline__ uint32_t cvt_tf32(float f) {
    uint32_t r;
    asm("cvt.rna.tf32.f32 %0, %1;" : "=r"(r) : "f"(f));
    return r;
}

__global__ void prep_kernel(const float* __restrict__ Uf,
                            const float* __restrict__ Uiou,
                            const float* __restrict__ Wiou) {
    int i = blockIdx.x * blockDim.x + threadIdx.x;
    if (i < 256 * 256) g_Wf[i] = __uint_as_float(cvt_tf32(Uf[i]));
    int j = i - 256 * 256;
    if (j >= 0 && j < 384 * 384) {
        int o = j / 384, k = j - o * 384;
        float v = (k < 256) ? Uiou[o * 256 + k] : Wiou[o * 128 + (k - 256)];
        g_Wiou[j] = __uint_as_float(cvt_tf32(v));
    }
}

__device__ __forceinline__ uint32_t smem_u32(const void* p) {
    uint32_t a;
    asm("{ .reg .u64 t; cvta.to.shared.u64 t, %1; cvt.u32.u64 %0, t; }"
        : "=r"(a) : "l"(p));
    return a;
}
// cp.async with source-size arg: sz==0 -> full zero-fill (leaf masking)
__device__ __forceinline__ void cpa16(uint32_t dst, const void* src, int sz) {
    asm volatile("cp.async.ca.shared.global [%0], [%1], 16, %2;"
                 :: "r"(dst), "l"(src), "r"(sz) : "memory");
}
#define CP_COMMIT() asm volatile("cp.async.commit_group;" ::: "memory")
#define WAITG(n)    asm volatile("cp.async.wait_group %0;" :: "n"(n) : "memory")

__device__ __forceinline__ void mma8(float d[4], const uint32_t a[4],
                                     const uint32_t b[2]) {
    asm volatile(
        "mma.sync.aligned.m16n8k8.row.col.f32.tf32.tf32.f32 "
        "{%0,%1,%2,%3}, {%4,%5,%6,%7}, {%8,%9}, {%0,%1,%2,%3};"
        : "+f"(d[0]), "+f"(d[1]), "+f"(d[2]), "+f"(d[3])
        : "r"(a[0]), "r"(a[1]), "r"(a[2]), "r"(a[3]), "r"(b[0]), "r"(b[1]));
}
__device__ __forceinline__ float sigm(float v) { return 1.0f / (1.0f + __expf(-v)); }

// ---- A chunk: global gather -> smem via cp.async (zfill masking) ----
template <int TYPE>
__device__ __forceinline__ void loadA(char* dst, int kc,
                                      const float* __restrict__ h,
                                      const float* __restrict__ x,
                                      const int* sCh, const int* sLf,
                                      int base, int tid) {
#pragma unroll
    for (int r = 0; r < 4; r++) {
        int idx = tid + r * 256;
        int m = idx >> 3, seg = idx & 7;
        int k = kc * KC + seg * 4;
        uint32_t d = smem_u32(dst + (m * PADK + seg * 4) * 4);
        const float* src;
        int sz = 16;
        if (TYPE == 0) {
            src = h + (size_t)sCh[2 * m + (k >> 7)] * HH + (k & 127);
        } else {
            int leaf = sLf[m];
            if (k < 256) {
                src = h + (size_t)sCh[2 * m + (k >> 7)] * HH + (k & 127);
                sz = leaf ? 0 : 16;
            } else {
                src = x + (size_t)(base + m) * HH + (k - 256);
                sz = leaf ? 16 : 0;
            }
        }
        cpa16(d, src, sz);
    }
}

__device__ __forceinline__ void loadB(const float* __restrict__ W, int ldw,
                                      int nb, char* dst, int kc, int tid) {
#pragma unroll
    for (int r = 0; r < 4; r++) {
        int idx = tid + r * 256;
        int n = idx >> 3, s = idx & 7;
        cpa16(smem_u32(dst + (n * PADK + s * 4) * 4),
              W + (size_t)(nb + n) * ldw + kc * KC + s * 4, 16);
    }
}

// ---- one K=32 chunk: pure LDS + MMA (A raw fp32 -> HW tf32 truncation) ----
__device__ __forceinline__ void compute_chunk(const float* sA, const float* sB,
                                              float acc[4][4][4],
                                              int wm, int wn, int g, int t) {
#pragma unroll
    for (int kk = 0; kk < 4; kk++) {
        uint32_t af[4][4];
#pragma unroll
        for (int mt = 0; mt < 4; mt++) {
            const float* ap = sA + (wm * 64 + mt * 16 + g) * PADK + kk * 8 + t;
            af[mt][0] = __float_as_uint(ap[0]);
            af[mt][1] = __float_as_uint(ap[8 * PADK]);
            af[mt][2] = __float_as_uint(ap[4]);
            af[mt][3] = __float_as_uint(ap[8 * PADK + 4]);
        }
        uint32_t bf[4][2];
#pragma unroll
        for (int nt = 0; nt < 4; nt++) {
            const float* bp = sB + (wn * 32 + nt * 8 + g) * PADK + kk * 8 + t;
            bf[nt][0] = __float_as_uint(bp[0]);
            bf[nt][1] = __float_as_uint(bp[4]);
        }
#pragma unroll
        for (int mt = 0; mt < 4; mt++)
#pragma unroll
            for (int nt = 0; nt < 4; nt++)
                mma8(acc[mt][nt], af[mt], bf[nt]);
    }
}

// ---- per-pass epilogue; biases via __ldg from global ----
template <int PASS>
__device__ __forceinline__ void epilogue(float acc[4][4][4],
                                         const float* __restrict__ c,
                                         const int* sCh, const int* sLf,
                                         const float* __restrict__ bUf,
                                         const float* __restrict__ bI,
                                         const float* __restrict__ bW,
                                         float* __restrict__ outH,
                                         float* __restrict__ outC,
                                         int base, int wm, int wn, int g, int t) {
#pragma unroll
    for (int mt = 0; mt < 4; mt++) {
#pragma unroll
        for (int hr = 0; hr < 2; hr++) {
            int row = wm * 64 + mt * 16 + hr * 8 + g;
            size_t node = (size_t)(base + row);
            const float* bb = sLf[row] ? bW : bI;
            const float* crow = c;
            if (PASS == 0) crow = c + (size_t)sCh[2 * row] * HH;
            if (PASS == 1) crow = c + (size_t)sCh[2 * row + 1] * HH;
#pragma unroll
            for (int nt = 0; nt < 4; nt++) {
                int col = wn * 32 + nt * 8 + 2 * t;
                float v0 = acc[mt][nt][hr * 2 + 0];
                float v1 = acc[mt][nt][hr * 2 + 1];
                if (PASS == 0) {
                    float2 bv = __ldg((const float2*)(bUf + col));
                    float2 cc = __ldg((const float2*)(crow + col));
                    *(float2*)(outC + node * HH + col) =
                        make_float2(sigm(v0 + bv.x) * cc.x,
                                    sigm(v1 + bv.y) * cc.y);
                } else if (PASS == 1) {
                    float2 bv = __ldg((const float2*)(bUf + 128 + col));
                    float2 cc = __ldg((const float2*)(crow + col));
                    float2 old = *(const float2*)(outC + node * HH + col);
                    *(float2*)(outC + node * HH + col) =
                        make_float2(old.x + sigm(v0 + bv.x) * cc.x,
                                    old.y + sigm(v1 + bv.y) * cc.y);
                } else if (PASS == 2) {
                    float2 bv = __ldg((const float2*)(bb + 256 + col));
                    *(float2*)(outH + node * HH + col) =
                        make_float2(tanhf(v0 + bv.x), tanhf(v1 + bv.y));
                } else if (PASS == 3) {
                    float2 bv = __ldg((const float2*)(bb + col));
                    float2 tu = *(const float2*)(outH + node * HH + col);
                    float2 cf = *(const float2*)(outC + node * HH + col);
                    *(float2*)(outC + node * HH + col) =
                        make_float2(sigm(v0 + bv.x) * tu.x + cf.x,
                                    sigm(v1 + bv.y) * tu.y + cf.y);
                } else {
                    float2 bv = __ldg((const float2*)(bb + 128 + col));
                    float2 cn = *(const float2*)(outC + node * HH + col);
                    *(float2*)(outH + node * HH + col) =
                        make_float2(sigm(v0 + bv.x) * tanhf(cn.x),
                                    sigm(v1 + bv.y) * tanhf(cn.y));
                }
            }
        }
    }
}

template <int PASS, int ATYPE, int NK>
__device__ __forceinline__ void run_pass(char* smem,
                                         const float* __restrict__ W, int ldw, int nb,
                                         const float* __restrict__ h,
                                         const float* __restrict__ x,
                                         const float* __restrict__ c,
                                         const int* sCh, const int* sLf,
                                         const float* __restrict__ bUf,
                                         const float* __restrict__ bI,
                                         const float* __restrict__ bW,
                                         float* outH, float* outC, int base,
                                         int tid, int wm, int wn, int g, int t) {
    float acc[4][4][4];
#pragma unroll
    for (int a1 = 0; a1 < 4; a1++)
#pragma unroll
        for (int a2 = 0; a2 < 4; a2++)
#pragma unroll
            for (int a3 = 0; a3 < 4; a3++) acc[a1][a2][a3] = 0.f;

    __syncthreads();   // all warps out of previous pass's smem slots

    // prologue: chunks 0,1 in flight (one commit group per chunk: A+B)
    loadA<ATYPE>(smem + A_OFF + 0 * SLOT, 0, h, x, sCh, sLf, base, tid);
    loadB(W, ldw, nb, smem + B_OFF + 0 * SLOT, 0, tid);
    CP_COMMIT();
    loadA<ATYPE>(smem + A_OFF + 1 * SLOT, 1, h, x, sCh, sLf, base, tid);
    loadB(W, ldw, nb, smem + B_OFF + 1 * SLOT, 1, tid);
    CP_COMMIT();

#pragma unroll 1
    for (int kc = 0; kc < NK; kc++) {
        if (kc < NK - 1) { WAITG(1); } else { WAITG(0); }  // chunk kc done
        __syncthreads();   // data visible to all; slot (kc+2)%3 free for reuse
        if (kc + 2 < NK) {
            loadA<ATYPE>(smem + A_OFF + ((kc + 2) % 3) * SLOT, kc + 2,
                         h, x, sCh, sLf, base, tid);
            loadB(W, ldw, nb, smem + B_OFF + ((kc + 2) % 3) * SLOT, kc + 2, tid);
            CP_COMMIT();
        }
        compute_chunk((const float*)(smem + A_OFF + (kc % 3) * SLOT),
                      (const float*)(smem + B_OFF + (kc % 3) * SLOT),
                      acc, wm, wn, g, t);
    }
    epilogue<PASS>(acc, c, sCh, sLf, bUf, bI, bW, outH, outC,
                   base, wm, wn, g, t);
}

__global__ void __launch_bounds__(256, 2)
tree_kernel(const float* __restrict__ x, const float* __restrict__ h,
            const float* __restrict__ c, const int* __restrict__ children,
            const int* __restrict__ is_leaf,
            const float* __restrict__ bWiou, const float* __restrict__ bUiou,
            const float* __restrict__ bUf,
            float* __restrict__ out, int N) {
    extern __shared__ char smem[];
    int* sCh = (int*)(smem + META_OFF);          // 256 i32
    int* sLf = (int*)(smem + META_OFF + 1024);   // 128 i32

    const int tid = threadIdx.x;
    const int wid = tid >> 5, lane = tid & 31;
    const int g = lane >> 2, t = lane & 3;
    const int wm = wid >> 2, wn = wid & 3;
    const int base = blockIdx.x * 128;

    sCh[tid] = children[base * 2 + tid];
    if (tid < 128) sLf[tid] = is_leaf[base + tid];
    __syncthreads();

    float* outH = out;
    float* outC = out + (size_t)N * HH;

    run_pass<0, 0, 8>(smem, g_Wf, 256, 0, h, x, c, sCh, sLf, bUf, bUiou, bWiou,
                      outH, outC, base, tid, wm, wn, g, t);
    run_pass<1, 0, 8>(smem, g_Wf, 256, 128, h, x, c, sCh, sLf, bUf, bUiou, bWiou,
                      outH, outC, base, tid, wm, wn, g, t);
    run_pass<2, 1, 12>(smem, g_Wiou, 384, 256, h, x, c, sCh, sLf, bUf, bUiou, bWiou,
                       outH, outC, base, tid, wm, wn, g, t);
    run_pass<3, 1, 12>(smem, g_Wiou, 384, 0, h, x, c, sCh, sLf, bUf, bUiou, bWiou,
                       outH, outC, base, tid, wm, wn, g, t);
    run_pass<4, 1, 12>(smem, g_Wiou, 384, 128, h, x, c, sCh, sLf, bUf, bUiou, bWiou,
                       outH, outC, base, tid, wm, wn, g, t);
}

extern "C" void kernel_launch(void* const* d_in, const int* in_sizes, int n_in,
                              void* d_out, int out_size) {
    const float* x        = (const float*)d_in[0];
    const float* h        = (const float*)d_in[1];
    const float* c        = (const float*)d_in[2];
    const int*   children = (const int*)d_in[3];
    const int*   is_leaf  = (const int*)d_in[4];
    const float* W_iou    = (const float*)d_in[5];
    const float* b_Wiou   = (const float*)d_in[6];
    const float* U_iou    = (const float*)d_in[7];
    const float* b_Uiou   = (const float*)d_in[8];
    const float* U_f      = (const float*)d_in[9];
    const float* b_Uf     = (const float*)d_in[10];

    int N = in_sizes[1] / HH;   // 400000, multiple of 128

    cudaFuncSetAttribute(tree_kernel,
                         cudaFuncAttributeMaxDynamicSharedMemorySize, SMEM_BYTES);

    prep_kernel<<<(256 * 256 + 384 * 384 + 255) / 256, 256>>>(U_f, U_iou, W_iou);
    tree_kernel<<<N / 128, 256, SMEM_BYTES>>>(x, h, c, children, is_leaf,
                                              b_Wiou, b_Uiou, b_Uf,
                                              (float*)d_out, N);
}